// round 2
// baseline (speedup 1.0000x reference)
#include <cuda_runtime.h>
#include <cuda_bf16.h>
#include <cstdint>

// Problem constants
#define MM 8192
#define NN 8192
#define KK 4096
#define K2 12288            // 3*KK: [a_hi | a_hi | a_lo] x [w_hi ; w_lo ; w_hi]
#define TM 128
#define TN 128
#define KS 64               // K elems per pipeline stage (128B rows)
#define STAGES 4
#define K_ITERS (K2 / KS)   // 192

// Static scratch (allocation-free rule: __device__ globals)
__device__ __nv_bfloat16 g_A2[(size_t)MM * K2];
__device__ __nv_bfloat16 g_Wt[(size_t)NN * K2];

// ---------------------------------------------------------------------------
// Prep kernel 1: A (fp32, MxK) -> A2 (bf16, M x 3K) = [a_hi | a_hi | a_lo]
// ---------------------------------------------------------------------------
__global__ void prep_a_kernel(const float* __restrict__ A, __nv_bfloat16* __restrict__ A2) {
    size_t idx = (size_t)blockIdx.x * blockDim.x + threadIdx.x;   // M*K/4 threads
    float4 v = reinterpret_cast<const float4*>(A)[idx];
    int m = (int)(idx >> 10);            // K/4 = 1024
    int c = ((int)idx & 1023) * 4;
    float x[4] = {v.x, v.y, v.z, v.w};
    union { __nv_bfloat16 b[4]; uint2 u; } H, L;
#pragma unroll
    for (int i = 0; i < 4; i++) {
        __nv_bfloat16 h = __float2bfloat16(x[i]);
        H.b[i] = h;
        L.b[i] = __float2bfloat16(x[i] - __bfloat162float(h));
    }
    __nv_bfloat16* row = A2 + (size_t)m * K2 + c;
    *reinterpret_cast<uint2*>(row)          = H.u;
    *reinterpret_cast<uint2*>(row + KK)     = H.u;
    *reinterpret_cast<uint2*>(row + 2 * KK) = L.u;
}

// ---------------------------------------------------------------------------
// Prep kernel 2: dequant int4 + transpose -> Wt (bf16, N x 3K) = [w_hi ; w_lo ; w_hi]
// ---------------------------------------------------------------------------
__global__ void prep_w_kernel(const int* __restrict__ Bp, const float* __restrict__ s,
                              __nv_bfloat16* __restrict__ Wt) {
    __shared__ __align__(16) __nv_bfloat16 sh[32][256];
    __shared__ __align__(16) __nv_bfloat16 sl[32][256];
    int tid = threadIdx.x;
    int n0  = blockIdx.x * 32;
    int kp0 = blockIdx.y * 32;          // packed-k base; k0 = kp0*8
#pragma unroll
    for (int rep = 0; rep < 4; rep++) {
        int kpi = (tid >> 5) + rep * 8;
        int ni  = tid & 31;
        int kp  = kp0 + kpi;
        int packed = Bp[(size_t)kp * NN + (n0 + ni)];
        float sv   = s[(size_t)(kp >> 4) * NN + (n0 + ni)];   // group = (kp*8)/128 = kp/16
#pragma unroll
        for (int j = 0; j < 8; j++) {
            int q = (packed >> (4 * j)) & 0xF;
            float w = (float)(q - 8) * sv;
            __nv_bfloat16 h = __float2bfloat16(w);
            sh[ni][kpi * 8 + j] = h;
            sl[ni][kpi * 8 + j] = __float2bfloat16(w - __bfloat162float(h));
        }
    }
    __syncthreads();
    int r  = tid >> 3;                  // 0..31 local n row
    int cb = (tid & 7) * 32;            // 0..224 local k base
    int k0 = kp0 * 8;
    __nv_bfloat16* row = Wt + (size_t)(n0 + r) * K2 + k0 + cb;
    const uint4* srcH = reinterpret_cast<const uint4*>(&sh[r][cb]);
    const uint4* srcL = reinterpret_cast<const uint4*>(&sl[r][cb]);
#pragma unroll
    for (int v = 0; v < 4; v++) {
        uint4 hv = srcH[v];
        uint4 lv = srcL[v];
        reinterpret_cast<uint4*>(row)[v]          = hv;   // w_hi  (pairs a_hi)
        reinterpret_cast<uint4*>(row + KK)[v]     = lv;   // w_lo  (pairs a_hi)
        reinterpret_cast<uint4*>(row + 2 * KK)[v] = hv;   // w_hi  (pairs a_lo)
    }
}

// ---------------------------------------------------------------------------
// sm80-style GEMM: C[M,N] = A2 @ Wt^T
// CTA tile 128x128, KS=64 per stage, 4-stage cp.async pipeline,
// 8 warps (4m x 2n), warp tile 32x64, mma.sync.m16n8k16 bf16.
// SMEM: per stage A 128x64 bf16 (16KB) + B 128x64 bf16 (16KB).
// Row = 128B = 8 x 16B chunks; chunk c of row r stored at (c ^ (r&7)).
// ---------------------------------------------------------------------------
#define STAGE_BYTES 16384
#define SMEM_BYTES (STAGES * STAGE_BYTES * 2)   // 131072

__device__ __forceinline__ uint32_t smem_u32(const void* p) {
    uint32_t a;
    asm("{ .reg .u64 t; cvta.to.shared.u64 t, %1; cvt.u32.u64 %0, t; }" : "=r"(a) : "l"(p));
    return a;
}

#define CP_ASYNC16(smem, gmem) \
    asm volatile("cp.async.cg.shared.global [%0], [%1], 16;" :: "r"(smem), "l"(gmem))
#define CP_COMMIT() asm volatile("cp.async.commit_group;" ::: "memory")
#define CP_WAIT2()  asm volatile("cp.async.wait_group 2;" ::: "memory")

#define LDSM_X4(r, addr) \
    asm volatile("ldmatrix.sync.aligned.m8n8.x4.shared.b16 {%0,%1,%2,%3}, [%4];" \
        : "=r"((r)[0]), "=r"((r)[1]), "=r"((r)[2]), "=r"((r)[3]) : "r"(addr))

#define MMA16816(d, a, b0, b1) \
    asm volatile("mma.sync.aligned.m16n8k16.row.col.f32.bf16.bf16.f32 " \
        "{%0,%1,%2,%3}, {%4,%5,%6,%7}, {%8,%9}, {%0,%1,%2,%3};" \
        : "+f"((d)[0]), "+f"((d)[1]), "+f"((d)[2]), "+f"((d)[3]) \
        : "r"((a)[0]), "r"((a)[1]), "r"((a)[2]), "r"((a)[3]), "r"(b0), "r"(b1))

__global__ __launch_bounds__(256, 1) void gemm_kernel(
    const __nv_bfloat16* __restrict__ gA,
    const __nv_bfloat16* __restrict__ gB,
    float* __restrict__ C)
{
    extern __shared__ char smem[];
    const uint32_t sbase = smem_u32(smem);
    const int tid = threadIdx.x, wid = tid >> 5, lid = tid & 31;

    // CTA swizzle: 8-wide m-bands sweeping n (L2 reuse)
    const int TILES_N = NN / TN;        // 64
    const int GW = 8;
    int bid  = blockIdx.x;
    int band = bid / (GW * TILES_N);
    int rem  = bid % (GW * TILES_N);
    int mt = band * GW + (rem % GW);
    int nt = rem / GW;
    const int m0 = mt * TM, n0 = nt * TN;

    const int warpM = (wid & 3) * 32;
    const int warpN = (wid >> 2) * 64;

    // Per-thread cp.async source/dest precompute
    // A chunks: i in [0,1024): row=i>>3, c=i&7. Same for B.
    const int c_row[4] = { (tid + 0) >> 3, (tid + 256) >> 3, (tid + 512) >> 3, (tid + 768) >> 3 };
    const int c_chk[4] = { tid & 7, tid & 7, tid & 7, tid & 7 };

    auto stage_load = [&](int st, int it) {
        const int k0 = it * KS;
        const uint32_t sa = sbase + st * STAGE_BYTES;
        const uint32_t sbuf = sbase + STAGES * STAGE_BYTES + st * STAGE_BYTES;
#pragma unroll
        for (int r = 0; r < 4; r++) {
            int row = c_row[r], c = c_chk[r];
            uint32_t soff = row * 128 + ((c ^ (row & 7)) << 4);
            CP_ASYNC16(sa + soff,   gA + (size_t)(m0 + row) * K2 + k0 + c * 8);
            CP_ASYNC16(sbuf + soff, gB + (size_t)(n0 + row) * K2 + k0 + c * 8);
        }
    };

    // Prologue: fill STAGES-1 stages
#pragma unroll
    for (int p = 0; p < STAGES - 1; p++) {
        stage_load(p, p);
        CP_COMMIT();
    }

    float acc[2][8][4];
#pragma unroll
    for (int mi = 0; mi < 2; mi++)
#pragma unroll
        for (int ni = 0; ni < 8; ni++)
#pragma unroll
            for (int v = 0; v < 4; v++) acc[mi][ni][v] = 0.f;

    // ldmatrix per-thread row/half within a 16x16 subtile
    const int lrow  = lid & 15;        // row within subtile
    const int lhalf = lid >> 4;        // k-half (0/1)

    for (int it = 0; it < K_ITERS; it++) {
        CP_WAIT2();
        __syncthreads();

        int ld = it + STAGES - 1;
        if (ld < K_ITERS) stage_load(ld % STAGES, ld);
        CP_COMMIT();

        const int st = it % STAGES;
        const uint32_t aBase = sbase + st * STAGE_BYTES;
        const uint32_t bBase = sbase + STAGES * STAGE_BYTES + st * STAGE_BYTES;

#pragma unroll
        for (int kt = 0; kt < 4; kt++) {
            const int c = kt * 2 + lhalf;
            uint32_t fa[2][4];
#pragma unroll
            for (int mi = 0; mi < 2; mi++) {
                int row = warpM + mi * 16 + lrow;
                LDSM_X4(fa[mi], aBase + row * 128 + ((c ^ (row & 7)) << 4));
            }
            uint32_t fb[4][4];
#pragma unroll
            for (int np = 0; np < 4; np++) {
                int row = warpN + np * 16 + lrow;
                LDSM_X4(fb[np], bBase + row * 128 + ((c ^ (row & 7)) << 4));
            }
#pragma unroll
            for (int mi = 0; mi < 2; mi++)
#pragma unroll
                for (int ni = 0; ni < 8; ni++) {
                    const int np = ni >> 1, h = ni & 1;
                    MMA16816(acc[mi][ni], fa[mi], fb[np][h], fb[np][2 + h]);
                }
        }
    }

    // Epilogue: direct fp32 stores (each thread owns (row, col..col+1) pairs)
#pragma unroll
    for (int mi = 0; mi < 2; mi++) {
        int row = m0 + warpM + mi * 16 + (lid >> 2);
#pragma unroll
        for (int ni = 0; ni < 8; ni++) {
            int col = n0 + warpN + ni * 8 + (lid & 3) * 2;
            float2 v0 = make_float2(acc[mi][ni][0], acc[mi][ni][1]);
            float2 v1 = make_float2(acc[mi][ni][2], acc[mi][ni][3]);
            *reinterpret_cast<float2*>(C + (size_t)row * NN + col)       = v0;
            *reinterpret_cast<float2*>(C + (size_t)(row + 8) * NN + col) = v1;
        }
    }
}

// ---------------------------------------------------------------------------
// Host launch
// ---------------------------------------------------------------------------
extern "C" void kernel_launch(void* const* d_in, const int* in_sizes, int n_in,
                              void* d_out, int out_size) {
    const float* A  = (const float*)d_in[0];
    const int*   Bp = (const int*)d_in[1];
    const float* sc = (const float*)d_in[2];
    float* C = (float*)d_out;

    void* pA2 = nullptr; void* pWt = nullptr;
    cudaGetSymbolAddress(&pA2, g_A2);
    cudaGetSymbolAddress(&pWt, g_Wt);

    prep_a_kernel<<<(MM * (KK / 4)) / 256, 256>>>(A, (__nv_bfloat16*)pA2);
    prep_w_kernel<<<dim3(NN / 32, (KK / 8) / 32), 256>>>(Bp, sc, (__nv_bfloat16*)pWt);

    static bool attr_set = false;
    if (!attr_set) {
        cudaFuncSetAttribute(gemm_kernel, cudaFuncAttributeMaxDynamicSharedMemorySize,
                             SMEM_BYTES);
        attr_set = true;
    }
    gemm_kernel<<<(MM / TM) * (NN / TN), 256, SMEM_BYTES>>>(
        (const __nv_bfloat16*)pA2, (const __nv_bfloat16*)pWt, C);
}

// round 3
// speedup vs baseline: 3.0085x; 3.0085x over previous
#include <cuda_runtime.h>
#include <cuda_fp16.h>
#include <cstdint>

// Problem constants
#define MM 8192
#define NN 8192
#define KK 4096
#define TM 128
#define TN 256
#define KS 64               // K elems per pipeline stage (128B rows)
#define STAGES 4
#define K_ITERS (KK / KS)   // 64

// Static scratch (allocation-free rule: __device__ globals): 64 MB + 64 MB
__device__ __half g_Ah[(size_t)MM * KK];
__device__ __half g_Wh[(size_t)NN * KK];

// ---------------------------------------------------------------------------
// Prep kernel 1: A (fp32, MxK) -> Ah (fp16, MxK). 8 elems/thread.
// ---------------------------------------------------------------------------
__global__ void prep_a_kernel(const float* __restrict__ A, __half* __restrict__ Ah) {
    size_t base = ((size_t)blockIdx.x * blockDim.x + threadIdx.x) * 8;
    float4 v0 = *reinterpret_cast<const float4*>(A + base);
    float4 v1 = *reinterpret_cast<const float4*>(A + base + 4);
    union { __half h[8]; uint4 u; } out;
    out.h[0] = __float2half(v0.x); out.h[1] = __float2half(v0.y);
    out.h[2] = __float2half(v0.z); out.h[3] = __float2half(v0.w);
    out.h[4] = __float2half(v1.x); out.h[5] = __float2half(v1.y);
    out.h[6] = __float2half(v1.z); out.h[7] = __float2half(v1.w);
    *reinterpret_cast<uint4*>(Ah + base) = out.u;
}

// ---------------------------------------------------------------------------
// Prep kernel 2: dequant int4 + transpose -> Wh (fp16, N x K), N-major rows.
// Block handles 32 n-cols x 256 k (32 packed rows); SMEM transpose.
// ---------------------------------------------------------------------------
__global__ void prep_w_kernel(const int* __restrict__ Bp, const float* __restrict__ s,
                              __half* __restrict__ Wh) {
    __shared__ __align__(16) __half sh[32][256];
    int tid = threadIdx.x;
    int n0  = blockIdx.x * 32;
    int kp0 = blockIdx.y * 32;          // packed-k base; k0 = kp0*8
#pragma unroll
    for (int rep = 0; rep < 4; rep++) {
        int kpi = (tid >> 5) + rep * 8;
        int ni  = tid & 31;
        int kp  = kp0 + kpi;
        int packed = Bp[(size_t)kp * NN + (n0 + ni)];
        float sv   = s[(size_t)(kp >> 4) * NN + (n0 + ni)];   // group = kp/16
#pragma unroll
        for (int j = 0; j < 8; j++) {
            int q = (packed >> (4 * j)) & 0xF;
            sh[ni][kpi * 8 + j] = __float2half((float)(q - 8) * sv);
        }
    }
    __syncthreads();
    int r  = tid >> 3;                  // 0..31 local n row
    int cb = (tid & 7) * 32;            // 0..224 local k base
    int k0 = kp0 * 8;
    __half* row = Wh + (size_t)(n0 + r) * KK + k0 + cb;
    const uint4* src = reinterpret_cast<const uint4*>(&sh[r][cb]);
#pragma unroll
    for (int v = 0; v < 4; v++)
        reinterpret_cast<uint4*>(row)[v] = src[v];
}

// ---------------------------------------------------------------------------
// GEMM: C[M,N] = Ah @ Wh^T (fp16 in, f32 acc)
// CTA 128x256, 8 warps (2m x 4n), warp tile 64x64, mma.sync.m16n8k16.
// 4-stage cp.async pipeline, KS=64. Row = 128B = 8 chunks; chunk swizzle c^(row&7).
// ---------------------------------------------------------------------------
#define A_STAGE_BYTES 16384              // 128 x 64 x 2
#define B_STAGE_BYTES 32768              // 256 x 64 x 2
#define SMEM_BYTES (STAGES * (A_STAGE_BYTES + B_STAGE_BYTES))   // 196608

__device__ __forceinline__ uint32_t smem_u32(const void* p) {
    uint32_t a;
    asm("{ .reg .u64 t; cvta.to.shared.u64 t, %1; cvt.u32.u64 %0, t; }" : "=r"(a) : "l"(p));
    return a;
}

#define CP_ASYNC16(smem, gmem) \
    asm volatile("cp.async.cg.shared.global [%0], [%1], 16;" :: "r"(smem), "l"(gmem))
#define CP_COMMIT() asm volatile("cp.async.commit_group;" ::: "memory")
#define CP_WAIT2()  asm volatile("cp.async.wait_group 2;" ::: "memory")

#define LDSM_X4(r, addr) \
    asm volatile("ldmatrix.sync.aligned.m8n8.x4.shared.b16 {%0,%1,%2,%3}, [%4];" \
        : "=r"((r)[0]), "=r"((r)[1]), "=r"((r)[2]), "=r"((r)[3]) : "r"(addr))

#define MMA16816(d, a, b0, b1) \
    asm volatile("mma.sync.aligned.m16n8k16.row.col.f32.f16.f16.f32 " \
        "{%0,%1,%2,%3}, {%4,%5,%6,%7}, {%8,%9}, {%0,%1,%2,%3};" \
        : "+f"((d)[0]), "+f"((d)[1]), "+f"((d)[2]), "+f"((d)[3]) \
        : "r"((a)[0]), "r"((a)[1]), "r"((a)[2]), "r"((a)[3]), "r"(b0), "r"(b1))

__global__ __launch_bounds__(256, 1) void gemm_kernel(
    const __half* __restrict__ gA,
    const __half* __restrict__ gB,
    float* __restrict__ C)
{
    extern __shared__ char smem[];
    const uint32_t sbase = smem_u32(smem);
    const int tid = threadIdx.x, wid = tid >> 5, lid = tid & 31;

    // CTA swizzle: 8-wide m-bands sweeping n (L2 reuse: 8MB A band resident)
    const int TILES_N = NN / TN;        // 32
    const int GW = 8;
    int bid  = blockIdx.x;
    int band = bid / (GW * TILES_N);
    int rem  = bid % (GW * TILES_N);
    const int m0 = (band * GW + (rem % GW)) * TM;
    const int n0 = (rem / GW) * TN;

    const int warpM = (wid & 1) * 64;   // 2 m-warps
    const int warpN = (wid >> 1) * 64;  // 4 n-warps

    auto stage_load = [&](int st, int it) {
        const int k0 = it * KS;
        const uint32_t sa = sbase + st * A_STAGE_BYTES;
        const uint32_t sb = sbase + STAGES * A_STAGE_BYTES + st * B_STAGE_BYTES;
        const int c = tid & 7;
#pragma unroll
        for (int r = 0; r < 4; r++) {                // A: 1024 chunks
            int row = (tid + r * 256) >> 3;
            uint32_t soff = row * 128 + ((c ^ (row & 7)) << 4);
            CP_ASYNC16(sa + soff, gA + (size_t)(m0 + row) * KK + k0 + c * 8);
        }
#pragma unroll
        for (int r = 0; r < 8; r++) {                // B: 2048 chunks
            int row = (tid + r * 256) >> 3;
            uint32_t soff = row * 128 + ((c ^ (row & 7)) << 4);
            CP_ASYNC16(sb + soff, gB + (size_t)(n0 + row) * KK + k0 + c * 8);
        }
    };

    // Prologue: fill STAGES-1 stages
#pragma unroll
    for (int p = 0; p < STAGES - 1; p++) {
        stage_load(p, p);
        CP_COMMIT();
    }

    float acc[4][8][4];
#pragma unroll
    for (int mi = 0; mi < 4; mi++)
#pragma unroll
        for (int ni = 0; ni < 8; ni++)
#pragma unroll
            for (int v = 0; v < 4; v++) acc[mi][ni][v] = 0.f;

    const int lrow  = lid & 15;        // row within 16-row subtile
    const int lhalf = lid >> 4;        // k-chunk half (0/1)

    for (int it = 0; it < K_ITERS; it++) {
        CP_WAIT2();
        __syncthreads();

        int ld = it + STAGES - 1;
        if (ld < K_ITERS) stage_load(ld % STAGES, ld);
        CP_COMMIT();

        const int st = it % STAGES;
        const uint32_t aBase = sbase + st * A_STAGE_BYTES;
        const uint32_t bBase = sbase + STAGES * A_STAGE_BYTES + st * B_STAGE_BYTES;

#pragma unroll
        for (int kt = 0; kt < 4; kt++) {
            const int c = kt * 2 + lhalf;
            uint32_t fa[4][4];
#pragma unroll
            for (int mi = 0; mi < 4; mi++) {
                int row = warpM + mi * 16 + lrow;
                LDSM_X4(fa[mi], aBase + row * 128 + ((c ^ (row & 7)) << 4));
            }
            uint32_t fb[4][4];
#pragma unroll
            for (int np = 0; np < 4; np++) {
                int row = warpN + np * 16 + lrow;
                LDSM_X4(fb[np], bBase + row * 128 + ((c ^ (row & 7)) << 4));
            }
#pragma unroll
            for (int mi = 0; mi < 4; mi++)
#pragma unroll
                for (int ni = 0; ni < 8; ni++) {
                    const int np = ni >> 1, h = ni & 1;
                    MMA16816(acc[mi][ni], fa[mi], fb[np][h], fb[np][2 + h]);
                }
        }
    }

    // Epilogue: direct fp32 stores
#pragma unroll
    for (int mi = 0; mi < 4; mi++) {
        int row = m0 + warpM + mi * 16 + (lid >> 2);
#pragma unroll
        for (int ni = 0; ni < 8; ni++) {
            int col = n0 + warpN + ni * 8 + (lid & 3) * 2;
            float2 v0 = make_float2(acc[mi][ni][0], acc[mi][ni][1]);
            float2 v1 = make_float2(acc[mi][ni][2], acc[mi][ni][3]);
            *reinterpret_cast<float2*>(C + (size_t)row * NN + col)       = v0;
            *reinterpret_cast<float2*>(C + (size_t)(row + 8) * NN + col) = v1;
        }
    }
}

// ---------------------------------------------------------------------------
// Host launch
// ---------------------------------------------------------------------------
extern "C" void kernel_launch(void* const* d_in, const int* in_sizes, int n_in,
                              void* d_out, int out_size) {
    const float* A  = (const float*)d_in[0];
    const int*   Bp = (const int*)d_in[1];
    const float* sc = (const float*)d_in[2];
    float* C = (float*)d_out;

    void* pAh = nullptr; void* pWh = nullptr;
    cudaGetSymbolAddress(&pAh, g_Ah);
    cudaGetSymbolAddress(&pWh, g_Wh);

    prep_a_kernel<<<(MM * (KK / 8)) / 256, 256>>>(A, (__half*)pAh);
    prep_w_kernel<<<dim3(NN / 32, (KK / 8) / 32), 256>>>(Bp, sc, (__half*)pWh);

    cudaFuncSetAttribute(gemm_kernel, cudaFuncAttributeMaxDynamicSharedMemorySize,
                         SMEM_BYTES);
    gemm_kernel<<<(MM / TM) * (NN / TN), 256, SMEM_BYTES>>>(
        (const __half*)pAh, (const __half*)pWh, C);
}